// round 9
// baseline (speedup 1.0000x reference)
#include <cuda_runtime.h>
#include <cuda_fp16.h>
#include <mma.h>

using namespace nvcuda;

#define T_ 4
#define B_ 32
#define C_ 384
#define N_ 256
#define HEADS_ 8
#define DH_ 48
#define MQK 768   // q rows [0,384) and k rows [384,768) stacked
#define K_ 384    // GEMM inner dim (both GEMMs)
#define MARGIN 4e-3f

static constexpr int BCN  = B_ * C_ * N_;        // 3,145,728
static constexpr int TBCN = T_ * BCN;            // 12,582,912

// ---------------- scratch (static device memory; no cudaMalloc allowed) ----
__device__ __half        g_s[TBCN];               // spikes [z][c][n] (GEMM B operand)
__device__ __half        g_sT[TBCN];              // spikes [z][n][c] (repair gathers)
__device__ unsigned char g_bits[(size_t)MQK * B_ * N_];  // 4 spike bits + flag(0x10)
__device__ __half        g_y[TBCN];               // attn*k, binary [z][c][n]
__device__ __half        g_Wqk_hi[MQK * K_];
__device__ float         g_Wqk_f32[MQK * K_];     // exact folded weights (repair)
__device__ __half        g_Wp_hi[C_ * K_];        // proj: hi-only (~1.7e-4)
__device__ float         g_bias_qk[MQK];
__device__ float         g_bias_p[C_];

// ---------------- K0: fold BN into weights ---------------------------------
__global__ void prep_weights(
    const float* __restrict__ qw, const float* __restrict__ qg, const float* __restrict__ qb,
    const float* __restrict__ qm, const float* __restrict__ qv,
    const float* __restrict__ kw, const float* __restrict__ kg, const float* __restrict__ kb,
    const float* __restrict__ km, const float* __restrict__ kv,
    const float* __restrict__ pw, const float* __restrict__ pbias, const float* __restrict__ pg,
    const float* __restrict__ pbeta, const float* __restrict__ pm, const float* __restrict__ pv)
{
    int idx = blockIdx.x * blockDim.x + threadIdx.x;
    if (idx < MQK * K_) {
        int d = idx / K_, c = idx % K_;
        float w, inv;
        if (d < C_) {
            inv = qg[d] / sqrtf(qv[d] + 1e-5f);
            w = qw[d * C_ + c] * inv;
        } else {
            int dd = d - C_;
            inv = kg[dd] / sqrtf(kv[dd] + 1e-5f);
            w = kw[dd * C_ + c] * inv;
        }
        g_Wqk_hi[idx]  = __float2half(w);
        g_Wqk_f32[idx] = w;
    }
    if (idx < C_ * K_) {
        int d = idx / K_;
        float inv = pg[d] / sqrtf(pv[d] + 1e-5f);
        g_Wp_hi[idx] = __float2half(pw[idx] * inv);
    }
    if (idx < MQK) {
        float inv, bias;
        if (idx < C_) {
            inv = qg[idx] / sqrtf(qv[idx] + 1e-5f);
            bias = qb[idx] - qm[idx] * inv;
        } else {
            int d = idx - C_;
            inv = kg[d] / sqrtf(kv[d] + 1e-5f);
            bias = kb[d] - km[d] * inv;
        }
        g_bias_qk[idx] = bias;
    }
    if (idx < C_) {
        float inv = pg[idx] / sqrtf(pv[idx] + 1e-5f);
        g_bias_p[idx] = pbias[idx] * inv + pbeta[idx] - pm[idx] * inv;
    }
}

// ---------------- K1: LIF over time -> spikes in BOTH layouts ---------------
__global__ __launch_bounds__(256) void lif_input2(
    const float* __restrict__ x, __half* __restrict__ s, __half* __restrict__ sT)
{
    __shared__ __half tile[T_][32][33];
    const int n0 = blockIdx.x * 32;
    const int c0 = blockIdx.y * 32;
    const int b  = blockIdx.z;
    const int tid = threadIdx.x;
    const int nl = tid & 31;
    const int cq = tid >> 5;

#pragma unroll
    for (int j = 0; j < 4; ++j) {
        const int cl = cq + j * 8;
        const int c  = c0 + cl;
        float v = 0.f;
#pragma unroll
        for (int t = 0; t < T_; ++t) {
            v = 0.5f * v + x[((size_t)(t * B_ + b) * C_ + c) * N_ + n0 + nl];
            if (v >= 1.0f) { tile[t][cl][nl] = __float2half(1.0f); v = 0.f; }
            else           { tile[t][cl][nl] = __float2half(0.0f); }
        }
    }
    __syncthreads();

    const int r2 = tid >> 3;
    const int q4 = (tid & 7) * 4;
#pragma unroll
    for (int t = 0; t < T_; ++t) {
        const size_t zb = (size_t)(t * B_ + b);
        {
            __half hv[4];
#pragma unroll
            for (int i = 0; i < 4; ++i) hv[i] = tile[t][r2][q4 + i];
            *(uint2*)(s + (zb * C_ + c0 + r2) * N_ + n0 + q4) = *(uint2*)hv;
        }
        {
            __half hv[4];
#pragma unroll
            for (int i = 0; i < 4; ++i) hv[i] = tile[t][q4 + i][r2];
            *(uint2*)(sT + (zb * N_ + n0 + r2) * C_ + c0 + q4) = *(uint2*)hv;
        }
    }
}

// ---------------- K2: fused GEMM + LIF -> spike bits ------------------------
// CTA = (Ntile 128, Mtile 64, b). Loops t=0..3: hi-only HMMA GEMM (z=t*32+b),
// stage fp32 tile in smem, LIF-update per-thread membranes (fixed (m,n)
// ownership across t), emit 4 spike bits + near-threshold flag per element.
// Eliminates the 100MB fp32 qk tensor: output is 6.3MB of bytes.
#define FBM 64
#define FBN 128
#define FBK 32
#define FSA_STRIDE (FBK + 8)   // 40 halfs
#define FSB_STRIDE (FBN + 8)   // 136 halfs
#define FUSED_SMEM 32768       // stage 64x128 fp32; tiles (13.8KB) overlap it

__global__ __launch_bounds__(256) void gemm_lif(
    const __half* __restrict__ A_hi,
    const __half* __restrict__ Bmat,     // s [z][c][n]
    const float* __restrict__ bias,
    unsigned char* __restrict__ bits)
{
    extern __shared__ char smem[];
    __half* sA   = (__half*)smem;                    // 64*40*2 = 5120 B
    __half* sB   = sA + FBM * FSA_STRIDE;            // 32*136*2 = 8704 B
    float* stage = (float*)smem;                     // 64*128*4 = 32 KB (reused)

    const int tileN = blockIdx.x * FBN;
    const int tileM = blockIdx.y * FBM;
    const int b     = blockIdx.z;

    const int tid  = threadIdx.x;
    const int warp = tid >> 5;
    const int wm   = warp & 1;    // 2 warps along M (32 rows)
    const int wn   = warp >> 1;   // 4 warps along N (32 cols)

    float v[8][4];
#pragma unroll
    for (int q = 0; q < 8; ++q)
#pragma unroll
        for (int l = 0; l < 4; ++l) v[q][l] = 0.f;
    unsigned int bitsReg[8] = {0, 0, 0, 0, 0, 0, 0, 0};

    // per-thread element ownership (fixed across t): e = tid + q*256
    const int em  = tid >> 5;            // row 0..63 base component
    const int en4 = (tid & 31) << 2;     // col (float4)

#pragma unroll
    for (int t = 0; t < T_; ++t) {
        const __half* Bz = Bmat + (size_t)(t * B_ + b) * K_ * N_;

        wmma::fragment<wmma::accumulator, 16, 16, 16, float> c[2][2];
#pragma unroll
        for (int i = 0; i < 2; i++)
#pragma unroll
            for (int j = 0; j < 2; j++) wmma::fill_fragment(c[i][j], 0.0f);

        for (int k0 = 0; k0 < K_; k0 += FBK) {
            // A tile 64x32: 256 uint4, 1/thread
            {
                int r  = tid >> 2;
                int ck = (tid & 3) << 3;
                *(uint4*)(sA + r * FSA_STRIDE + ck) =
                    *(const uint4*)(A_hi + (size_t)(tileM + r) * K_ + k0 + ck);
            }
            // B tile 32x128: 512 uint4, 2/thread
#pragma unroll
            for (int i = 0; i < 2; i++) {
                int vv = tid + i * 256;
                int r  = vv >> 4;
                int cn = (vv & 15) << 3;
                *(uint4*)(sB + r * FSB_STRIDE + cn) =
                    *(const uint4*)(Bz + (size_t)(k0 + r) * N_ + tileN + cn);
            }
            __syncthreads();

#pragma unroll
            for (int kk = 0; kk < 2; ++kk) {
                wmma::fragment<wmma::matrix_b, 16, 16, 16, __half, wmma::row_major> bfr[2];
#pragma unroll
                for (int j = 0; j < 2; j++)
                    wmma::load_matrix_sync(bfr[j], sB + kk * 16 * FSB_STRIDE + wn * 32 + j * 16, FSB_STRIDE);
                wmma::fragment<wmma::matrix_a, 16, 16, 16, __half, wmma::row_major> afr;
#pragma unroll
                for (int i = 0; i < 2; i++) {
                    wmma::load_matrix_sync(afr, sA + (wm * 32 + i * 16) * FSA_STRIDE + kk * 16, FSA_STRIDE);
#pragma unroll
                    for (int j = 0; j < 2; j++) wmma::mma_sync(c[i][j], afr, bfr[j], c[i][j]);
                }
            }
            __syncthreads();
        }

        // stage fp32 tile (overlaps sA/sB -- tiles are dead here)
#pragma unroll
        for (int i = 0; i < 2; i++)
#pragma unroll
            for (int j = 0; j < 2; j++)
                wmma::store_matrix_sync(stage + (wm * 32 + i * 16) * FBN + wn * 32 + j * 16,
                                        c[i][j], FBN, wmma::mem_row_major);
        __syncthreads();

        // LIF update on owned elements
#pragma unroll
        for (int q = 0; q < 8; ++q) {
            const int m = em + (q << 3) * 4 / 32;  // placeholder, replaced below
            (void)m;
        }
#pragma unroll
        for (int q = 0; q < 8; ++q) {
            int e  = tid + q * 256;      // 0..2047
            int m  = e >> 5;             // 0..63
            float4 val = *(float4*)(stage + m * FBN + en4);
            float bb = bias[tileM + m];
            float xv[4] = {val.x + bb, val.y + bb, val.z + bb, val.w + bb};
#pragma unroll
            for (int l = 0; l < 4; ++l) {
                v[q][l] = 0.5f * v[q][l] + xv[l];
                if (fabsf(v[q][l] - 1.0f) < MARGIN)
                    bitsReg[q] |= (0x10u << (8 * l));
                if (v[q][l] >= 1.0f) {
                    bitsReg[q] |= ((1u << t) << (8 * l));
                    v[q][l] = 0.f;
                }
            }
        }
        __syncthreads();
    }

    // write bits: [row][b][n] bytes, uint32 (4 n) per write
#pragma unroll
    for (int q = 0; q < 8; ++q) {
        int e = tid + q * 256;
        int m = e >> 5;
        size_t off = ((size_t)(tileM + m) * B_ + b) * N_ + tileN + en4;
        *(unsigned int*)(bits + off) = bitsReg[q];
    }
}

// ---------------- K4: wmma GEMM (hi-only) -----------------------------------
#define BM 128
#define BN 128
#define BK 32
#define SA_STRIDE (BK + 8)   // 40 halfs
#define SB_STRIDE (BN + 8)   // 136 halfs
#define GEMM_SMEM 32768

__global__ __launch_bounds__(256) void gemm_hi(
    const __half* __restrict__ A_hi,
    const __half* __restrict__ Bmat,
    const float* __restrict__ bias,
    float* __restrict__ Out,
    int M)
{
    extern __shared__ char smem[];
    __half* sA_hi = (__half*)smem;
    __half* sB    = sA_hi + BM * SA_STRIDE;
    float* stage  = (float*)smem;

    const int z     = blockIdx.z;
    const int tileM = blockIdx.y * BM;
    const int tileN = blockIdx.x * BN;
    const __half* Bz = Bmat + (size_t)z * K_ * N_;
    float* Oz = Out + (size_t)z * M * N_;

    const int tid  = threadIdx.x;
    const int warp = tid >> 5;
    const int wm   = warp & 3;
    const int wn   = warp >> 2;

    wmma::fragment<wmma::accumulator, 16, 16, 16, float> c[2][4];
#pragma unroll
    for (int i = 0; i < 2; i++)
#pragma unroll
        for (int j = 0; j < 4; j++) wmma::fill_fragment(c[i][j], 0.0f);

    for (int k0 = 0; k0 < K_; k0 += BK) {
#pragma unroll
        for (int i = 0; i < 2; i++) {
            int v  = tid + i * 256;
            int r  = v >> 2;
            int ck = (v & 3) << 3;
            *(uint4*)(sA_hi + r * SA_STRIDE + ck) =
                *(const uint4*)(A_hi + (size_t)(tileM + r) * K_ + k0 + ck);
        }
#pragma unroll
        for (int i = 0; i < 2; i++) {
            int v  = tid + i * 256;
            int r  = v >> 4;
            int cn = (v & 15) << 3;
            *(uint4*)(sB + r * SB_STRIDE + cn) =
                *(const uint4*)(Bz + (size_t)(k0 + r) * N_ + tileN + cn);
        }
        __syncthreads();

#pragma unroll
        for (int kk = 0; kk < 2; ++kk) {
            wmma::fragment<wmma::matrix_b, 16, 16, 16, __half, wmma::row_major> bfr[4];
#pragma unroll
            for (int j = 0; j < 4; j++)
                wmma::load_matrix_sync(bfr[j], sB + kk * 16 * SB_STRIDE + wn * 64 + j * 16, SB_STRIDE);
            wmma::fragment<wmma::matrix_a, 16, 16, 16, __half, wmma::row_major> afr;
#pragma unroll
            for (int i = 0; i < 2; i++) {
                wmma::load_matrix_sync(afr, sA_hi + (wm * 32 + i * 16) * SA_STRIDE + kk * 16, SA_STRIDE);
#pragma unroll
                for (int j = 0; j < 4; j++) wmma::mma_sync(c[i][j], afr, bfr[j], c[i][j]);
            }
        }
        __syncthreads();
    }

#pragma unroll
    for (int rnd = 0; rnd < 2; ++rnd) {
        if ((wm >> 1) == rnd) {
#pragma unroll
            for (int i = 0; i < 2; i++)
#pragma unroll
                for (int j = 0; j < 4; j++)
                    wmma::store_matrix_sync(stage + ((wm & 1) * 32 + i * 16) * BN + wn * 64 + j * 16,
                                            c[i][j], BN, wmma::mem_row_major);
        }
        __syncthreads();
#pragma unroll
        for (int q = 0; q < 8; ++q) {
            int v  = tid + q * 256;
            int m  = v >> 5;
            int n4 = (v & 31) << 2;
            float4 val = *(float4*)(stage + m * BN + n4);
            float bb = bias[tileM + rnd * 64 + m];
            val.x += bb; val.y += bb; val.z += bb; val.w += bb;
            *(float4*)(Oz + (size_t)(tileM + rnd * 64 + m) * N_ + tileN + n4) = val;
        }
        __syncthreads();
    }
}

// ---------------- K3: bits -> repair -> attn gate -> y -----------------------
#define LISTCAP 3072

__global__ __launch_bounds__(256) void spike_attn3(
    const unsigned char* __restrict__ bitsIn,
    const float* __restrict__ alpha_p,
    const __half* __restrict__ sT,
    const float* __restrict__ W32,
    const float* __restrict__ bias,
    __half* __restrict__ y)
{
    __shared__ unsigned char sBits[96][32];   // [0,48)=q chains, [48,96)=k chains
    __shared__ unsigned short list[LISTCAP];
    __shared__ int cnt;
    __shared__ float sS[8][T_][32];

    const int blk = blockIdx.x;
    const int n0  = (blk & 7) << 5;
    const int hh  = (blk >> 3) & (HEADS_ - 1);
    const int b   = blk >> 6;
    const int tid  = threadIdx.x;
    const int g    = tid >> 5;
    const int lane = tid & 31;
    const float alpha = *alpha_p;

    if (tid == 0) cnt = 0;
    __syncthreads();

    // ---- phase 1: gather precomputed bits; queue flagged chains ----
    {
        const int nloc = lane;
        const int n = n0 + nloc;
#pragma unroll
        for (int d = 0; d < 6; ++d) {
            const int dh = g * 6 + d;
#pragma unroll
            for (int side = 0; side < 2; ++side) {
                const int row = side * C_ + hh * DH_ + dh;
                unsigned byte = bitsIn[((size_t)row * B_ + b) * N_ + n];
                const int chain = side * 48 + dh;
                sBits[chain][nloc] = (unsigned char)(byte & 0xFu);
                if (byte & 0x10u) {
                    int idx = atomicAdd(&cnt, 1);
                    if (idx < LISTCAP)
                        list[idx] = (unsigned short)((chain << 5) | nloc);
                }
            }
        }
    }
    __syncthreads();

    // ---- phase 2: exact fp32 repair (one warp per flagged chain) ----
    {
        const int m = min(cnt, LISTCAP);
        for (int e = g; e < m; e += 8) {
            const int ent   = list[e];
            const int chain = ent >> 5;
            const int nloc  = ent & 31;
            const int row   = (chain < 48) ? (hh * DH_ + chain)
                                           : (C_ + hh * DH_ + (chain - 48));
            const int n = n0 + nloc;
            const float* wrow = W32 + (size_t)row * K_;
            float v = 0.f; unsigned bits = 0;
#pragma unroll
            for (int t = 0; t < T_; ++t) {
                const __half* scol = sT + ((size_t)(t * B_ + b) * N_ + n) * C_;
                float part = 0.f;
#pragma unroll
                for (int c = 0; c < K_ / 32; ++c) {
                    int cc = lane + c * 32;
                    part += wrow[cc] * __half2float(scol[cc]);
                }
#pragma unroll
                for (int o = 16; o; o >>= 1)
                    part += __shfl_xor_sync(0xFFFFFFFFu, part, o);
                float val = part + bias[row];
                v = 0.5f * v + val;
                if (v >= 1.0f) { bits |= (1u << t); v = 0.f; }
            }
            if (lane == 0) sBits[chain][nloc] = (unsigned char)bits;
        }
    }
    __syncthreads();

    // ---- phase 3: popcounts -> attn gate -> y ----
    const int nloc = lane;
    const int n = n0 + nloc;
    float S[T_] = {0.f, 0.f, 0.f, 0.f};
    unsigned kbyte[6];
#pragma unroll
    for (int d = 0; d < 6; ++d) {
        unsigned qb = sBits[g * 6 + d][nloc];
        kbyte[d]    = sBits[48 + g * 6 + d][nloc];
#pragma unroll
        for (int t = 0; t < T_; ++t) S[t] += (float)((qb >> t) & 1u);
    }
#pragma unroll
    for (int t = 0; t < T_; ++t) sS[g][t][nloc] = S[t];
    __syncthreads();

    float St[T_];
#pragma unroll
    for (int t = 0; t < T_; ++t) {
        float acc = 0.f;
#pragma unroll
        for (int gg = 0; gg < 8; ++gg) acc += sS[gg][t][nloc];
        St[t] = acc;
    }

    const float om = 1.0f - alpha;
    float m2 = alpha * St[0] + om * St[1];
    float qs[T_];
    qs[0] = St[0] + St[0];
    qs[1] = St[0] + St[1];
    qs[2] = m2 + St[2];
    qs[3] = alpha * m2 + om * St[2] + St[3];

    const __half one  = __float2half(1.0f);
    const __half zero = __float2half(0.0f);
    const int rowq = hh * DH_ + g * 6;
    float v = 0.f;
#pragma unroll
    for (int t = 0; t < T_; ++t) {
        v = 0.5f * v + qs[t];
        bool fire = false;
        if (v >= 0.5f) { fire = true; v = 0.f; }
        size_t base = ((size_t)(t * B_ + b) * C_ + rowq) * N_ + n;
#pragma unroll
        for (int d = 0; d < 6; ++d)
            y[base + (size_t)d * N_] = (fire && ((kbyte[d] >> t) & 1u)) ? one : zero;
    }
}

// ---------------- launch ---------------------------------------------------
extern "C" void kernel_launch(void* const* d_in, const int* in_sizes, int n_in,
                              void* d_out, int out_size)
{
    (void)in_sizes; (void)n_in; (void)out_size;
    const float* x       = (const float*)d_in[0];
    const float* q_w     = (const float*)d_in[1];
    const float* q_gamma = (const float*)d_in[2];
    const float* q_beta  = (const float*)d_in[3];
    const float* q_mean  = (const float*)d_in[4];
    const float* q_var   = (const float*)d_in[5];
    const float* k_w     = (const float*)d_in[6];
    const float* k_gamma = (const float*)d_in[7];
    const float* k_beta  = (const float*)d_in[8];
    const float* k_mean  = (const float*)d_in[9];
    const float* k_var   = (const float*)d_in[10];
    const float* proj_w  = (const float*)d_in[11];
    const float* proj_b  = (const float*)d_in[12];
    const float* proj_g  = (const float*)d_in[13];
    const float* proj_be = (const float*)d_in[14];
    const float* proj_m  = (const float*)d_in[15];
    const float* proj_v  = (const float*)d_in[16];
    const float* m_alpha = (const float*)d_in[17];
    float* out = (float*)d_out;

    __half *s_p, *sT_p, *y_p, *wqk_hi, *wp_hi;
    unsigned char* bits_p;
    float *bias_qk, *bias_p, *w32_p;
    cudaGetSymbolAddress((void**)&s_p,     g_s);
    cudaGetSymbolAddress((void**)&sT_p,    g_sT);
    cudaGetSymbolAddress((void**)&y_p,     g_y);
    cudaGetSymbolAddress((void**)&wqk_hi,  g_Wqk_hi);
    cudaGetSymbolAddress((void**)&w32_p,   g_Wqk_f32);
    cudaGetSymbolAddress((void**)&wp_hi,   g_Wp_hi);
    cudaGetSymbolAddress((void**)&bits_p,  g_bits);
    cudaGetSymbolAddress((void**)&bias_qk, g_bias_qk);
    cudaGetSymbolAddress((void**)&bias_p,  g_bias_p);

    cudaFuncSetAttribute(gemm_hi,  cudaFuncAttributeMaxDynamicSharedMemorySize, GEMM_SMEM);
    cudaFuncSetAttribute(gemm_lif, cudaFuncAttributeMaxDynamicSharedMemorySize, FUSED_SMEM);

    // K0: weight prep (BN fold; q/k hi + exact fp32; proj hi-only)
    prep_weights<<<(MQK * K_) / 256, 256>>>(q_w, q_gamma, q_beta, q_mean, q_var,
                                            k_w, k_gamma, k_beta, k_mean, k_var,
                                            proj_w, proj_b, proj_g, proj_be, proj_m, proj_v);
    // K1: LIF(x) -> s ([z][c][n]) and sT ([z][n][c])
    lif_input2<<<dim3(N_ / 32, C_ / 32, B_), 256>>>(x, s_p, sT_p);
    // K2: fused hi-only GEMM + LIF -> spike-bit bytes (no qk tensor)
    gemm_lif<<<dim3(N_ / FBN, MQK / FBM, B_), 256, FUSED_SMEM>>>(
        wqk_hi, s_p, bias_qk, bits_p);
    // K3: bits + exact threshold repair + attn gate -> y
    spike_attn3<<<B_ * HEADS_ * (N_ / 32), 256>>>(bits_p, m_alpha, sT_p, w32_p, bias_qk, y_p);
    // K4: out = Wp'_hi @ y + bias_p
    gemm_hi<<<dim3(N_ / BN, C_ / BM, T_ * B_), 256, GEMM_SMEM>>>(
        wp_hi, y_p, bias_p, out, C_);
}

// round 10
// speedup vs baseline: 1.2639x; 1.2639x over previous
#include <cuda_runtime.h>
#include <cuda_fp16.h>
#include <mma.h>

using namespace nvcuda;

#define T_ 4
#define B_ 32
#define C_ 384
#define N_ 256
#define HEADS_ 8
#define DH_ 48
#define MQK 768   // q rows [0,384) and k rows [384,768) stacked
#define K_ 384    // GEMM inner dim (both GEMMs)

static constexpr int BCN  = B_ * C_ * N_;        // 3,145,728
static constexpr int TBCN = T_ * BCN;            // 12,582,912

// ---------------- scratch (static device memory; no cudaMalloc allowed) ----
__device__ __half g_s[TBCN];                          // spikes [z][c][n] (GEMM B)
__device__ __half g_sT[TBCN];                         // spikes [z][n][c] (repair gathers)
__device__ __half g_qk[(size_t)T_ * B_ * MQK * N_];   // hi-only BN(conv(s)), fp16
__device__ __half g_y[TBCN];                          // attn*k, binary [z][c][n]
__device__ __half g_Wqk_hi[MQK * K_];
__device__ float  g_Wqk_f32[MQK * K_];                // exact folded weights (repair)
__device__ __half g_Wp_hi[C_ * K_];                   // proj: hi-only (~1.7e-4)
__device__ float  g_bias_qk[MQK];
__device__ float  g_bias_p[C_];

// ---------------- K0: fold BN into weights ---------------------------------
__global__ void prep_weights(
    const float* __restrict__ qw, const float* __restrict__ qg, const float* __restrict__ qb,
    const float* __restrict__ qm, const float* __restrict__ qv,
    const float* __restrict__ kw, const float* __restrict__ kg, const float* __restrict__ kb,
    const float* __restrict__ km, const float* __restrict__ kv,
    const float* __restrict__ pw, const float* __restrict__ pbias, const float* __restrict__ pg,
    const float* __restrict__ pbeta, const float* __restrict__ pm, const float* __restrict__ pv)
{
    int idx = blockIdx.x * blockDim.x + threadIdx.x;
    if (idx < MQK * K_) {
        int d = idx / K_, c = idx % K_;
        float w, inv;
        if (d < C_) {
            inv = qg[d] / sqrtf(qv[d] + 1e-5f);
            w = qw[d * C_ + c] * inv;
        } else {
            int dd = d - C_;
            inv = kg[dd] / sqrtf(kv[dd] + 1e-5f);
            w = kw[dd * C_ + c] * inv;
        }
        g_Wqk_hi[idx]  = __float2half(w);
        g_Wqk_f32[idx] = w;
    }
    if (idx < C_ * K_) {
        int d = idx / K_;
        float inv = pg[d] / sqrtf(pv[d] + 1e-5f);
        g_Wp_hi[idx] = __float2half(pw[idx] * inv);
    }
    if (idx < MQK) {
        float inv, bias;
        if (idx < C_) {
            inv = qg[idx] / sqrtf(qv[idx] + 1e-5f);
            bias = qb[idx] - qm[idx] * inv;
        } else {
            int d = idx - C_;
            inv = kg[d] / sqrtf(kv[d] + 1e-5f);
            bias = kb[d] - km[d] * inv;
        }
        g_bias_qk[idx] = bias;
    }
    if (idx < C_) {
        float inv = pg[idx] / sqrtf(pv[idx] + 1e-5f);
        g_bias_p[idx] = pbias[idx] * inv + pbeta[idx] - pm[idx] * inv;
    }
}

// ---------------- K1: LIF over time -> spikes in BOTH layouts ---------------
__global__ __launch_bounds__(256) void lif_input2(
    const float* __restrict__ x, __half* __restrict__ s, __half* __restrict__ sT)
{
    __shared__ __half tile[T_][32][33];
    const int n0 = blockIdx.x * 32;
    const int c0 = blockIdx.y * 32;
    const int b  = blockIdx.z;
    const int tid = threadIdx.x;
    const int nl = tid & 31;
    const int cq = tid >> 5;

#pragma unroll
    for (int j = 0; j < 4; ++j) {
        const int cl = cq + j * 8;
        const int c  = c0 + cl;
        float v = 0.f;
#pragma unroll
        for (int t = 0; t < T_; ++t) {
            v = 0.5f * v + x[((size_t)(t * B_ + b) * C_ + c) * N_ + n0 + nl];
            if (v >= 1.0f) { tile[t][cl][nl] = __float2half(1.0f); v = 0.f; }
            else           { tile[t][cl][nl] = __float2half(0.0f); }
        }
    }
    __syncthreads();

    const int r2 = tid >> 3;
    const int q4 = (tid & 7) * 4;
#pragma unroll
    for (int t = 0; t < T_; ++t) {
        const size_t zb = (size_t)(t * B_ + b);
        {
            __half hv[4];
#pragma unroll
            for (int i = 0; i < 4; ++i) hv[i] = tile[t][r2][q4 + i];
            *(uint2*)(s + (zb * C_ + c0 + r2) * N_ + n0 + q4) = *(uint2*)hv;
        }
        {
            __half hv[4];
#pragma unroll
            for (int i = 0; i < 4; ++i) hv[i] = tile[t][q4 + i][r2];
            *(uint2*)(sT + (zb * N_ + n0 + r2) * C_ + c0 + q4) = *(uint2*)hv;
        }
    }
}

// ---------------- K2/K4: wmma GEMM (hi-only, m32n8k16 fragments) -----------
// Out[z] = A_hi @ B[z] + bias. Warp tile 64x32 via 32x8 accumulators:
// fragment loads per kk = A 2KB + B 1KB per warp -> 48KB smem reads per
// k-iter for the CTA (vs 96KB with 16x16 frags) -> below the HMMA floor.
#define BM 128
#define BN 128
#define BK 32
#define SA_STRIDE (BK + 8)   // 40 halfs
#define SB_STRIDE (BN + 8)   // 136 halfs
#define GEMM_SMEM 32768      // epilogue staging 64x128 fp32 dominates

template<bool HOUT>
__global__ __launch_bounds__(256) void gemm_hi(
    const __half* __restrict__ A_hi,
    const __half* __restrict__ Bmat,
    const float* __restrict__ bias,
    void* __restrict__ OutV,
    int M)
{
    extern __shared__ char smem[];
    __half* sA_hi = (__half*)smem;                   // 10240 B
    __half* sB    = sA_hi + BM * SA_STRIDE;          // 8704 B
    float* stage  = (float*)smem;                    // epilogue reuse 32 KB

    const int z     = blockIdx.z;
    const int tileM = blockIdx.y * BM;
    const int tileN = blockIdx.x * BN;
    const __half* Bz = Bmat + (size_t)z * K_ * N_;

    const int tid  = threadIdx.x;
    const int warp = tid >> 5;
    const int wm   = warp & 1;    // 2 warps along M (64 rows each)
    const int wn   = warp >> 1;   // 4 warps along N (32 cols each)

    wmma::fragment<wmma::accumulator, 32, 8, 16, float> c[2][4];
#pragma unroll
    for (int i = 0; i < 2; i++)
#pragma unroll
        for (int j = 0; j < 4; j++) wmma::fill_fragment(c[i][j], 0.0f);

    for (int k0 = 0; k0 < K_; k0 += BK) {
#pragma unroll
        for (int i = 0; i < 2; i++) {
            int v  = tid + i * 256;
            int r  = v >> 2;
            int ck = (v & 3) << 3;
            *(uint4*)(sA_hi + r * SA_STRIDE + ck) =
                *(const uint4*)(A_hi + (size_t)(tileM + r) * K_ + k0 + ck);
        }
#pragma unroll
        for (int i = 0; i < 2; i++) {
            int v  = tid + i * 256;
            int r  = v >> 4;
            int cn = (v & 15) << 3;
            *(uint4*)(sB + r * SB_STRIDE + cn) =
                *(const uint4*)(Bz + (size_t)(k0 + r) * N_ + tileN + cn);
        }
        __syncthreads();

#pragma unroll
        for (int kk = 0; kk < 2; ++kk) {
            wmma::fragment<wmma::matrix_b, 32, 8, 16, __half, wmma::row_major> bfr[4];
#pragma unroll
            for (int j = 0; j < 4; j++)
                wmma::load_matrix_sync(bfr[j], sB + kk * 16 * SB_STRIDE + wn * 32 + j * 8, SB_STRIDE);
            wmma::fragment<wmma::matrix_a, 32, 8, 16, __half, wmma::row_major> afr;
#pragma unroll
            for (int i = 0; i < 2; i++) {
                wmma::load_matrix_sync(afr, sA_hi + (wm * 64 + i * 32) * SA_STRIDE + kk * 16, SA_STRIDE);
#pragma unroll
                for (int j = 0; j < 4; j++) wmma::mma_sync(c[i][j], afr, bfr[j], c[i][j]);
            }
        }
        __syncthreads();
    }

    // epilogue: two 64-row rounds through 32KB staging (+bias), coalesced
#pragma unroll
    for (int rnd = 0; rnd < 2; ++rnd) {
        if (wm == rnd) {
#pragma unroll
            for (int i = 0; i < 2; i++)
#pragma unroll
                for (int j = 0; j < 4; j++)
                    wmma::store_matrix_sync(stage + (i * 32) * BN + wn * 32 + j * 8,
                                            c[i][j], BN, wmma::mem_row_major);
        }
        __syncthreads();
#pragma unroll
        for (int q = 0; q < 8; ++q) {
            int v  = tid + q * 256;        // 0..2047
            int m  = v >> 5;               // row 0..63
            int n4 = (v & 31) << 2;        // col (x4)
            float4 val = *(float4*)(stage + m * BN + n4);
            float bb = bias[tileM + rnd * 64 + m];
            size_t off = (size_t)z * M * N_ + (size_t)(tileM + rnd * 64 + m) * N_ + tileN + n4;
            if (HOUT) {
                __half h[4];
                h[0] = __float2half(val.x + bb);
                h[1] = __float2half(val.y + bb);
                h[2] = __float2half(val.z + bb);
                h[3] = __float2half(val.w + bb);
                *(uint2*)((__half*)OutV + off) = *(uint2*)h;
            } else {
                val.x += bb; val.y += bb; val.z += bb; val.w += bb;
                *(float4*)((float*)OutV + off) = val;
            }
        }
        __syncthreads();
    }
}

// ---------------- K3: spike attn with exact threshold repair ----------------
// Phase 1: approx LIF on fp16 hi-only qk; dynamic error bound
//   e_t = 0.5*e_{t-1} + 1.5e-3 (hi-GEMM bound w/ slack) + |x|*6e-4 (fp16 ulp),
//   e resets on spike (both paths reset v to exactly 0). Flag if |v-1| < e.
// Phase 2: warp-cooperative exact fp32 recompute of flagged chains.
// Phase 3: exact S_t popcounts -> attn gate -> y = attn & k.
#define LISTCAP 3072

__global__ __launch_bounds__(256) void spike_attn2(
    const __half* __restrict__ qk,
    const float* __restrict__ alpha_p,
    const __half* __restrict__ sT,
    const float* __restrict__ W32,
    const float* __restrict__ bias,
    __half* __restrict__ y)
{
    __shared__ unsigned char sBits[96][32];   // chains: [0,48)=q, [48,96)=k
    __shared__ unsigned short list[LISTCAP];
    __shared__ int cnt;
    __shared__ float sS[8][T_][32];

    const int blk = blockIdx.x;
    const int n0  = (blk & 7) << 5;
    const int hh  = (blk >> 3) & (HEADS_ - 1);
    const int b   = blk >> 6;
    const int tid  = threadIdx.x;
    const int g    = tid >> 5;
    const int lane = tid & 31;
    const float alpha = *alpha_p;

    if (tid == 0) cnt = 0;
    __syncthreads();

    // ---- phase 1: approx chains + flags ----
    {
        const int nloc = lane;
        const int n = n0 + nloc;
#pragma unroll
        for (int d = 0; d < 6; ++d) {
            const int dh = g * 6 + d;
#pragma unroll
            for (int side = 0; side < 2; ++side) {
                const int row = side * C_ + hh * DH_ + dh;
                float v = 0.f, e = 0.f;
                unsigned bits = 0; bool flag = false;
#pragma unroll
                for (int t = 0; t < T_; ++t) {
                    float val = __half2float(qk[((size_t)(t * B_ + b) * MQK + row) * N_ + n]);
                    v = 0.5f * v + val;
                    e = 0.5f * e + 1.5e-3f + fabsf(val) * 6e-4f;
                    if (fabsf(v - 1.0f) < e) flag = true;
                    if (v >= 1.0f) { bits |= (1u << t); v = 0.f; e = 0.f; }
                }
                const int chain = side * 48 + dh;
                sBits[chain][nloc] = (unsigned char)bits;
                if (flag) {
                    int idx = atomicAdd(&cnt, 1);
                    if (idx < LISTCAP)
                        list[idx] = (unsigned short)((chain << 5) | nloc);
                }
            }
        }
    }
    __syncthreads();

    // ---- phase 2: exact repair (one warp per flagged chain) ----
    {
        const int m = min(cnt, LISTCAP);
        for (int e = g; e < m; e += 8) {
            const int ent   = list[e];
            const int chain = ent >> 5;
            const int nloc  = ent & 31;
            const int row   = (chain < 48) ? (hh * DH_ + chain)
                                           : (C_ + hh * DH_ + (chain - 48));
            const int n = n0 + nloc;
            const float* wrow = W32 + (size_t)row * K_;
            float v = 0.f; unsigned bits = 0;
#pragma unroll
            for (int t = 0; t < T_; ++t) {
                const __half* scol = sT + ((size_t)(t * B_ + b) * N_ + n) * C_;
                float part = 0.f;
#pragma unroll
                for (int c = 0; c < K_ / 32; ++c) {
                    int cc = lane + c * 32;
                    part += wrow[cc] * __half2float(scol[cc]);
                }
#pragma unroll
                for (int o = 16; o; o >>= 1)
                    part += __shfl_xor_sync(0xFFFFFFFFu, part, o);
                float val = part + bias[row];
                v = 0.5f * v + val;
                if (v >= 1.0f) { bits |= (1u << t); v = 0.f; }
            }
            if (lane == 0) sBits[chain][nloc] = (unsigned char)bits;
        }
    }
    __syncthreads();

    // ---- phase 3: exact popcounts -> attn -> y ----
    const int nloc = lane;
    const int n = n0 + nloc;
    float S[T_] = {0.f, 0.f, 0.f, 0.f};
    unsigned kbyte[6];
#pragma unroll
    for (int d = 0; d < 6; ++d) {
        unsigned qb = sBits[g * 6 + d][nloc];
        kbyte[d]    = sBits[48 + g * 6 + d][nloc];
#pragma unroll
        for (int t = 0; t < T_; ++t) S[t] += (float)((qb >> t) & 1u);
    }
#pragma unroll
    for (int t = 0; t < T_; ++t) sS[g][t][nloc] = S[t];
    __syncthreads();

    float St[T_];
#pragma unroll
    for (int t = 0; t < T_; ++t) {
        float acc = 0.f;
#pragma unroll
        for (int gg = 0; gg < 8; ++gg) acc += sS[gg][t][nloc];
        St[t] = acc;
    }

    const float om = 1.0f - alpha;
    float m2 = alpha * St[0] + om * St[1];
    float qs[T_];
    qs[0] = St[0] + St[0];
    qs[1] = St[0] + St[1];
    qs[2] = m2 + St[2];
    qs[3] = alpha * m2 + om * St[2] + St[3];

    const __half one  = __float2half(1.0f);
    const __half zero = __float2half(0.0f);
    const int rowq = hh * DH_ + g * 6;
    float v = 0.f;
#pragma unroll
    for (int t = 0; t < T_; ++t) {
        v = 0.5f * v + qs[t];
        bool fire = false;
        if (v >= 0.5f) { fire = true; v = 0.f; }
        size_t base = ((size_t)(t * B_ + b) * C_ + rowq) * N_ + n;
#pragma unroll
        for (int d = 0; d < 6; ++d)
            y[base + (size_t)d * N_] = (fire && ((kbyte[d] >> t) & 1u)) ? one : zero;
    }
}

// ---------------- launch ---------------------------------------------------
extern "C" void kernel_launch(void* const* d_in, const int* in_sizes, int n_in,
                              void* d_out, int out_size)
{
    (void)in_sizes; (void)n_in; (void)out_size;
    const float* x       = (const float*)d_in[0];
    const float* q_w     = (const float*)d_in[1];
    const float* q_gamma = (const float*)d_in[2];
    const float* q_beta  = (const float*)d_in[3];
    const float* q_mean  = (const float*)d_in[4];
    const float* q_var   = (const float*)d_in[5];
    const float* k_w     = (const float*)d_in[6];
    const float* k_gamma = (const float*)d_in[7];
    const float* k_beta  = (const float*)d_in[8];
    const float* k_mean  = (const float*)d_in[9];
    const float* k_var   = (const float*)d_in[10];
    const float* proj_w  = (const float*)d_in[11];
    const float* proj_b  = (const float*)d_in[12];
    const float* proj_g  = (const float*)d_in[13];
    const float* proj_be = (const float*)d_in[14];
    const float* proj_m  = (const float*)d_in[15];
    const float* proj_v  = (const float*)d_in[16];
    const float* m_alpha = (const float*)d_in[17];
    float* out = (float*)d_out;

    __half *s_p, *sT_p, *y_p, *wqk_hi, *wp_hi, *qk_p;
    float *bias_qk, *bias_p, *w32_p;
    cudaGetSymbolAddress((void**)&s_p,     g_s);
    cudaGetSymbolAddress((void**)&sT_p,    g_sT);
    cudaGetSymbolAddress((void**)&y_p,     g_y);
    cudaGetSymbolAddress((void**)&wqk_hi,  g_Wqk_hi);
    cudaGetSymbolAddress((void**)&w32_p,   g_Wqk_f32);
    cudaGetSymbolAddress((void**)&wp_hi,   g_Wp_hi);
    cudaGetSymbolAddress((void**)&qk_p,    g_qk);
    cudaGetSymbolAddress((void**)&bias_qk, g_bias_qk);
    cudaGetSymbolAddress((void**)&bias_p,  g_bias_p);

    cudaFuncSetAttribute(gemm_hi<true>,  cudaFuncAttributeMaxDynamicSharedMemorySize, GEMM_SMEM);
    cudaFuncSetAttribute(gemm_hi<false>, cudaFuncAttributeMaxDynamicSharedMemorySize, GEMM_SMEM);

    // K0: weight prep (BN fold; q/k hi + exact fp32; proj hi-only)
    prep_weights<<<(MQK * K_) / 256, 256>>>(q_w, q_gamma, q_beta, q_mean, q_var,
                                            k_w, k_gamma, k_beta, k_mean, k_var,
                                            proj_w, proj_b, proj_g, proj_be, proj_m, proj_v);
    // K1: LIF(x) -> s ([z][c][n]) and sT ([z][n][c])
    lif_input2<<<dim3(N_ / 32, C_ / 32, B_), 256>>>(x, s_p, sT_p);
    // K2: qk = [Wq';Wk']_hi @ s + bias  (hi-only, fp16 out; repaired in K3)
    gemm_hi<true><<<dim3(N_ / BN, MQK / BM, T_ * B_), 256, GEMM_SMEM>>>(
        wqk_hi, s_p, bias_qk, qk_p, MQK);
    // K3: approx spikes + exact threshold repair + attn gate -> y
    spike_attn2<<<B_ * HEADS_ * (N_ / 32), 256>>>(qk_p, m_alpha, sT_p, w32_p, bias_qk, y_p);
    // K4: out = Wp'_hi @ y + bias_p (fp32 out)
    gemm_hi<false><<<dim3(N_ / BN, C_ / BM, T_ * B_), 256, GEMM_SMEM>>>(
        wp_hi, y_p, bias_p, out, C_);
}

// round 11
// speedup vs baseline: 1.3088x; 1.0356x over previous
#include <cuda_runtime.h>
#include <cuda_fp16.h>
#include <mma.h>

using namespace nvcuda;

#define T_ 4
#define B_ 32
#define C_ 384
#define N_ 256
#define HEADS_ 8
#define DH_ 48
#define MQK 768   // q rows [0,384) and k rows [384,768) stacked
#define K_ 384    // GEMM inner dim (both GEMMs)

static constexpr int BCN  = B_ * C_ * N_;        // 3,145,728
static constexpr int TBCN = T_ * BCN;            // 12,582,912

// ---------------- scratch (static device memory; no cudaMalloc allowed) ----
__device__ __half g_sT[TBCN];                         // spikes [z][n][c] (K2 B^T + repair)
__device__ __half g_qk[(size_t)T_ * B_ * MQK * N_];   // hi-only BN(conv(s)), fp16
__device__ __half g_y[TBCN];                          // attn*k, binary [z][c][n] (K4 B)
__device__ __half g_Wqk_hi[MQK * K_];
__device__ float  g_Wqk_f32[MQK * K_];                // exact folded weights (repair)
__device__ __half g_Wp_hi[C_ * K_];                   // proj: hi-only (~1.7e-4)
__device__ float  g_bias_qk[MQK];
__device__ float  g_bias_p[C_];

// ---------------- K0: fold BN into weights ---------------------------------
__global__ void prep_weights(
    const float* __restrict__ qw, const float* __restrict__ qg, const float* __restrict__ qb,
    const float* __restrict__ qm, const float* __restrict__ qv,
    const float* __restrict__ kw, const float* __restrict__ kg, const float* __restrict__ kb,
    const float* __restrict__ km, const float* __restrict__ kv,
    const float* __restrict__ pw, const float* __restrict__ pbias, const float* __restrict__ pg,
    const float* __restrict__ pbeta, const float* __restrict__ pm, const float* __restrict__ pv)
{
    int idx = blockIdx.x * blockDim.x + threadIdx.x;
    if (idx < MQK * K_) {
        int d = idx / K_, c = idx % K_;
        float w, inv;
        if (d < C_) {
            inv = qg[d] / sqrtf(qv[d] + 1e-5f);
            w = qw[d * C_ + c] * inv;
        } else {
            int dd = d - C_;
            inv = kg[dd] / sqrtf(kv[dd] + 1e-5f);
            w = kw[dd * C_ + c] * inv;
        }
        g_Wqk_hi[idx]  = __float2half(w);
        g_Wqk_f32[idx] = w;
    }
    if (idx < C_ * K_) {
        int d = idx / K_;
        float inv = pg[d] / sqrtf(pv[d] + 1e-5f);
        g_Wp_hi[idx] = __float2half(pw[idx] * inv);
    }
    if (idx < MQK) {
        float inv, bias;
        if (idx < C_) {
            inv = qg[idx] / sqrtf(qv[idx] + 1e-5f);
            bias = qb[idx] - qm[idx] * inv;
        } else {
            int d = idx - C_;
            inv = kg[d] / sqrtf(kv[d] + 1e-5f);
            bias = kb[d] - km[d] * inv;
        }
        g_bias_qk[idx] = bias;
    }
    if (idx < C_) {
        float inv = pg[idx] / sqrtf(pv[idx] + 1e-5f);
        g_bias_p[idx] = pbias[idx] * inv + pbeta[idx] - pm[idx] * inv;
    }
}

// ---------------- K1: LIF over time -> spikes, [z][n][c] only ---------------
__global__ __launch_bounds__(256) void lif_inputT(
    const float* __restrict__ x, __half* __restrict__ sT)
{
    __shared__ __half tile[T_][32][33];
    const int n0 = blockIdx.x * 32;
    const int c0 = blockIdx.y * 32;
    const int b  = blockIdx.z;
    const int tid = threadIdx.x;
    const int nl = tid & 31;
    const int cq = tid >> 5;

#pragma unroll
    for (int j = 0; j < 4; ++j) {
        const int cl = cq + j * 8;
        const int c  = c0 + cl;
        float v = 0.f;
#pragma unroll
        for (int t = 0; t < T_; ++t) {
            v = 0.5f * v + x[((size_t)(t * B_ + b) * C_ + c) * N_ + n0 + nl];
            if (v >= 1.0f) { tile[t][cl][nl] = __float2half(1.0f); v = 0.f; }
            else           { tile[t][cl][nl] = __float2half(0.0f); }
        }
    }
    __syncthreads();

    const int r2 = tid >> 3;           // n 0..31
    const int q4 = (tid & 7) * 4;      // c by 4
#pragma unroll
    for (int t = 0; t < T_; ++t) {
        __half hv[4];
#pragma unroll
        for (int i = 0; i < 4; ++i) hv[i] = tile[t][q4 + i][r2];
        *(uint2*)(sT + ((size_t)(t * B_ + b) * N_ + n0 + r2) * C_ + c0 + q4) = *(uint2*)hv;
    }
}

// ---------------- K2/K4: wmma GEMM (hi-only, m32n8k16) ---------------------
// Out[z] = A_hi @ B[z] + bias. BCOL: B read from sT [z][n][c] (B^T) with
// col-major fragments; else row-major [z][c][n].
#define BM 128
#define BN 128
#define BK 32
#define SA_STRIDE (BK + 8)    // 40 halfs
#define SB_STRIDE (BN + 8)    // 136 halfs (row-major B tile)
#define SBT_STRIDE (BK + 8)   // 40 halfs (col-major B tile: 128 n-rows x 32 k)
#define GEMM_SMEM 32768       // epilogue staging 64x128 fp32 dominates

template<bool HOUT, bool BCOL>
__global__ __launch_bounds__(256) void gemm_hi(
    const __half* __restrict__ A_hi,
    const __half* __restrict__ Bmat,
    const float* __restrict__ bias,
    void* __restrict__ OutV,
    int M)
{
    extern __shared__ char smem[];
    __half* sA_hi = (__half*)smem;                   // 10240 B
    __half* sB    = sA_hi + BM * SA_STRIDE;          // row: 8704 B / col: 10240 B
    float* stage  = (float*)smem;                    // epilogue reuse 32 KB

    const int z     = blockIdx.z;
    const int tileM = blockIdx.y * BM;
    const int tileN = blockIdx.x * BN;
    const __half* Bz = Bmat + (size_t)z * K_ * N_;   // same volume either layout

    const int tid  = threadIdx.x;
    const int warp = tid >> 5;
    const int wm   = warp & 1;    // 2 warps along M (64 rows each)
    const int wn   = warp >> 1;   // 4 warps along N (32 cols each)

    wmma::fragment<wmma::accumulator, 32, 8, 16, float> c[2][4];
#pragma unroll
    for (int i = 0; i < 2; i++)
#pragma unroll
        for (int j = 0; j < 4; j++) wmma::fill_fragment(c[i][j], 0.0f);

    for (int k0 = 0; k0 < K_; k0 += BK) {
#pragma unroll
        for (int i = 0; i < 2; i++) {
            int v  = tid + i * 256;
            int r  = v >> 2;
            int ck = (v & 3) << 3;
            *(uint4*)(sA_hi + r * SA_STRIDE + ck) =
                *(const uint4*)(A_hi + (size_t)(tileM + r) * K_ + k0 + ck);
        }
        if (BCOL) {
            // B^T tile: 128 n-rows x 32 k halfs from sT[z][n][c]
#pragma unroll
            for (int i = 0; i < 2; i++) {
                int v  = tid + i * 256;
                int r  = v >> 2;            // n 0..127
                int ck = (v & 3) << 3;      // k by 8
                *(uint4*)(sB + r * SBT_STRIDE + ck) =
                    *(const uint4*)(Bz + (size_t)(tileN + r) * K_ + k0 + ck);
            }
        } else {
            // B tile: 32 k-rows x 128 n halfs from y[z][c][n]
#pragma unroll
            for (int i = 0; i < 2; i++) {
                int v  = tid + i * 256;
                int r  = v >> 4;
                int cn = (v & 15) << 3;
                *(uint4*)(sB + r * SB_STRIDE + cn) =
                    *(const uint4*)(Bz + (size_t)(k0 + r) * N_ + tileN + cn);
            }
        }
        __syncthreads();

#pragma unroll
        for (int kk = 0; kk < 2; ++kk) {
            wmma::fragment<wmma::matrix_a, 32, 8, 16, __half, wmma::row_major> afr[2];
#pragma unroll
            for (int i = 0; i < 2; i++)
                wmma::load_matrix_sync(afr[i], sA_hi + (wm * 64 + i * 32) * SA_STRIDE + kk * 16, SA_STRIDE);
            if (BCOL) {
                wmma::fragment<wmma::matrix_b, 32, 8, 16, __half, wmma::col_major> bfr[4];
#pragma unroll
                for (int j = 0; j < 4; j++)
                    wmma::load_matrix_sync(bfr[j], sB + (wn * 32 + j * 8) * SBT_STRIDE + kk * 16, SBT_STRIDE);
#pragma unroll
                for (int i = 0; i < 2; i++)
#pragma unroll
                    for (int j = 0; j < 4; j++) wmma::mma_sync(c[i][j], afr[i], bfr[j], c[i][j]);
            } else {
                wmma::fragment<wmma::matrix_b, 32, 8, 16, __half, wmma::row_major> bfr[4];
#pragma unroll
                for (int j = 0; j < 4; j++)
                    wmma::load_matrix_sync(bfr[j], sB + kk * 16 * SB_STRIDE + wn * 32 + j * 8, SB_STRIDE);
#pragma unroll
                for (int i = 0; i < 2; i++)
#pragma unroll
                    for (int j = 0; j < 4; j++) wmma::mma_sync(c[i][j], afr[i], bfr[j], c[i][j]);
            }
        }
        __syncthreads();
    }

    // epilogue: two 64-row rounds through 32KB staging (+bias), coalesced
#pragma unroll
    for (int rnd = 0; rnd < 2; ++rnd) {
        if (wm == rnd) {
#pragma unroll
            for (int i = 0; i < 2; i++)
#pragma unroll
                for (int j = 0; j < 4; j++)
                    wmma::store_matrix_sync(stage + (i * 32) * BN + wn * 32 + j * 8,
                                            c[i][j], BN, wmma::mem_row_major);
        }
        __syncthreads();
#pragma unroll
        for (int q = 0; q < 8; ++q) {
            int v  = tid + q * 256;
            int m  = v >> 5;
            int n4 = (v & 31) << 2;
            float4 val = *(float4*)(stage + m * BN + n4);
            float bb = bias[tileM + rnd * 64 + m];
            size_t off = (size_t)z * M * N_ + (size_t)(tileM + rnd * 64 + m) * N_ + tileN + n4;
            if (HOUT) {
                __half h[4];
                h[0] = __float2half(val.x + bb);
                h[1] = __float2half(val.y + bb);
                h[2] = __float2half(val.z + bb);
                h[3] = __float2half(val.w + bb);
                *(uint2*)((__half*)OutV + off) = *(uint2*)h;
            } else {
                val.x += bb; val.y += bb; val.z += bb; val.w += bb;
                *(float4*)((float*)OutV + off) = val;
            }
        }
        __syncthreads();
    }
}

// ---------------- K3: spike attn, half2 n-pairs + exact repair --------------
// Block = (b, head, 64-n chunk); warp g owns dh group (6 ch) x 2 sides; each
// lane processes an n-pair via half2 (full 128B/warp loads). Dynamic flag
// margin e_t = 0.5 e + 1.5e-3 + |x|*6e-4 (resets on spike); flagged chains
// recomputed exactly in fp32. LISTCAP == total chains -> no overflow possible.
#define LISTCAP 6144

__global__ __launch_bounds__(256) void spike_attn2(
    const __half* __restrict__ qk,
    const float* __restrict__ alpha_p,
    const __half* __restrict__ sT,
    const float* __restrict__ W32,
    const float* __restrict__ bias,
    __half* __restrict__ y)
{
    __shared__ unsigned char sBits[96][64];    // [0,48)=q chains, [48,96)=k
    __shared__ unsigned short list[LISTCAP];
    __shared__ int cnt;
    __shared__ float sS[8][T_][64];

    const int blk = blockIdx.x;
    const int n0  = (blk & 3) << 6;            // 4 chunks of 64 n
    const int hh  = (blk >> 2) & (HEADS_ - 1);
    const int b   = blk >> 5;
    const int tid  = threadIdx.x;
    const int g    = tid >> 5;
    const int lane = tid & 31;
    const int nA   = lane * 2;                 // local n pair
    const float alpha = *alpha_p;

    if (tid == 0) cnt = 0;
    __syncthreads();

    // ---- phase 1: approx chains (2 n per thread) + flags ----
    {
        const int n = n0 + nA;
#pragma unroll
        for (int d = 0; d < 6; ++d) {
            const int dh = g * 6 + d;
#pragma unroll
            for (int side = 0; side < 2; ++side) {
                const int row = side * C_ + hh * DH_ + dh;
                float vx = 0.f, vy = 0.f, ex = 0.f, ey = 0.f;
                unsigned bL = 0, bH = 0;
                bool fL = false, fH = false;
#pragma unroll
                for (int t = 0; t < T_; ++t) {
                    __half2 hv = *(const __half2*)(qk + ((size_t)(t * B_ + b) * MQK + row) * N_ + n);
                    float2 val = __half22float2(hv);
                    vx = 0.5f * vx + val.x;
                    ex = 0.5f * ex + 1.5e-3f + fabsf(val.x) * 6e-4f;
                    if (fabsf(vx - 1.0f) < ex) fL = true;
                    if (vx >= 1.0f) { bL |= (1u << t); vx = 0.f; ex = 0.f; }
                    vy = 0.5f * vy + val.y;
                    ey = 0.5f * ey + 1.5e-3f + fabsf(val.y) * 6e-4f;
                    if (fabsf(vy - 1.0f) < ey) fH = true;
                    if (vy >= 1.0f) { bH |= (1u << t); vy = 0.f; ey = 0.f; }
                }
                const int chain = side * 48 + dh;
                sBits[chain][nA]     = (unsigned char)bL;
                sBits[chain][nA + 1] = (unsigned char)bH;
                if (fL) list[atomicAdd(&cnt, 1)] = (unsigned short)((chain << 6) | nA);
                if (fH) list[atomicAdd(&cnt, 1)] = (unsigned short)((chain << 6) | (nA + 1));
            }
        }
    }
    __syncthreads();

    // ---- phase 2: exact fp32 repair (one warp per flagged chain) ----
    {
        const int m = cnt;
        for (int e = g; e < m; e += 8) {
            const int ent   = list[e];
            const int chain = ent >> 6;
            const int nloc  = ent & 63;
            const int row   = (chain < 48) ? (hh * DH_ + chain)
                                           : (C_ + hh * DH_ + (chain - 48));
            const int n = n0 + nloc;
            const float* wrow = W32 + (size_t)row * K_;
            float v = 0.f; unsigned bits = 0;
#pragma unroll
            for (int t = 0; t < T_; ++t) {
                const __half* scol = sT + ((size_t)(t * B_ + b) * N_ + n) * C_;
                float part = 0.f;
#pragma unroll
                for (int cix = 0; cix < K_ / 32; ++cix) {
                    int cc = lane + cix * 32;
                    part += wrow[cc] * __half2float(scol[cc]);
                }
#pragma unroll
                for (int o = 16; o; o >>= 1)
                    part += __shfl_xor_sync(0xFFFFFFFFu, part, o);
                float val = part + bias[row];
                v = 0.5f * v + val;
                if (v >= 1.0f) { bits |= (1u << t); v = 0.f; }
            }
            if (lane == 0) sBits[chain][nloc] = (unsigned char)bits;
        }
    }
    __syncthreads();

    // ---- phase 3: popcounts -> attn gate -> y (half2 stores) ----
    float SA[T_] = {0.f, 0.f, 0.f, 0.f};
    float SBv[T_] = {0.f, 0.f, 0.f, 0.f};
    unsigned kbA[6], kbB[6];
#pragma unroll
    for (int d = 0; d < 6; ++d) {
        unsigned qA = sBits[g * 6 + d][nA];
        unsigned qB = sBits[g * 6 + d][nA + 1];
        kbA[d] = sBits[48 + g * 6 + d][nA];
        kbB[d] = sBits[48 + g * 6 + d][nA + 1];
#pragma unroll
        for (int t = 0; t < T_; ++t) {
            SA[t]  += (float)((qA >> t) & 1u);
            SBv[t] += (float)((qB >> t) & 1u);
        }
    }
#pragma unroll
    for (int t = 0; t < T_; ++t) {
        sS[g][t][nA]     = SA[t];
        sS[g][t][nA + 1] = SBv[t];
    }
    __syncthreads();

    float StA[T_], StB[T_];
#pragma unroll
    for (int t = 0; t < T_; ++t) {
        float aA = 0.f, aB = 0.f;
#pragma unroll
        for (int gg = 0; gg < 8; ++gg) { aA += sS[gg][t][nA]; aB += sS[gg][t][nA + 1]; }
        StA[t] = aA; StB[t] = aB;
    }

    const float om = 1.0f - alpha;
    float m2A = alpha * StA[0] + om * StA[1];
    float m2B = alpha * StB[0] + om * StB[1];
    float qsA[T_], qsB[T_];
    qsA[0] = StA[0] + StA[0];        qsB[0] = StB[0] + StB[0];
    qsA[1] = StA[0] + StA[1];        qsB[1] = StB[0] + StB[1];
    qsA[2] = m2A + StA[2];           qsB[2] = m2B + StB[2];
    qsA[3] = alpha * m2A + om * StA[2] + StA[3];
    qsB[3] = alpha * m2B + om * StB[2] + StB[3];

    const int rowq = hh * DH_ + g * 6;
    float vA = 0.f, vB = 0.f;
#pragma unroll
    for (int t = 0; t < T_; ++t) {
        vA = 0.5f * vA + qsA[t];
        vB = 0.5f * vB + qsB[t];
        bool fA = false, fB = false;
        if (vA >= 0.5f) { fA = true; vA = 0.f; }
        if (vB >= 0.5f) { fB = true; vB = 0.f; }
        size_t base = ((size_t)(t * B_ + b) * C_ + rowq) * N_ + n0 + nA;
#pragma unroll
        for (int d = 0; d < 6; ++d) {
            __half h2[2];
            h2[0] = (fA && ((kbA[d] >> t) & 1u)) ? __float2half(1.0f) : __float2half(0.0f);
            h2[1] = (fB && ((kbB[d] >> t) & 1u)) ? __float2half(1.0f) : __float2half(0.0f);
            *(uint*)(y + base + (size_t)d * N_) = *(uint*)h2;
        }
    }
}

// ---------------- launch ---------------------------------------------------
extern "C" void kernel_launch(void* const* d_in, const int* in_sizes, int n_in,
                              void* d_out, int out_size)
{
    (void)in_sizes; (void)n_in; (void)out_size;
    const float* x       = (const float*)d_in[0];
    const float* q_w     = (const float*)d_in[1];
    const float* q_gamma = (const float*)d_in[2];
    const float* q_beta  = (const float*)d_in[3];
    const float* q_mean  = (const float*)d_in[4];
    const float* q_var   = (const float*)d_in[5];
    const float* k_w     = (const float*)d_in[6];
    const float* k_gamma = (const float*)d_in[7];
    const float* k_beta  = (const float*)d_in[8];
    const float* k_mean  = (const float*)d_in[9];
    const float* k_var   = (const float*)d_in[10];
    const float* proj_w  = (const float*)d_in[11];
    const float* proj_b  = (const float*)d_in[12];
    const float* proj_g  = (const float*)d_in[13];
    const float* proj_be = (const float*)d_in[14];
    const float* proj_m  = (const float*)d_in[15];
    const float* proj_v  = (const float*)d_in[16];
    const float* m_alpha = (const float*)d_in[17];
    float* out = (float*)d_out;

    __half *sT_p, *y_p, *wqk_hi, *wp_hi, *qk_p;
    float *bias_qk, *bias_p, *w32_p;
    cudaGetSymbolAddress((void**)&sT_p,    g_sT);
    cudaGetSymbolAddress((void**)&y_p,     g_y);
    cudaGetSymbolAddress((void**)&wqk_hi,  g_Wqk_hi);
    cudaGetSymbolAddress((void**)&w32_p,   g_Wqk_f32);
    cudaGetSymbolAddress((void**)&wp_hi,   g_Wp_hi);
    cudaGetSymbolAddress((void**)&qk_p,    g_qk);
    cudaGetSymbolAddress((void**)&bias_qk, g_bias_qk);
    cudaGetSymbolAddress((void**)&bias_p,  g_bias_p);

    cudaFuncSetAttribute((gemm_hi<true, true>),   cudaFuncAttributeMaxDynamicSharedMemorySize, GEMM_SMEM);
    cudaFuncSetAttribute((gemm_hi<false, false>), cudaFuncAttributeMaxDynamicSharedMemorySize, GEMM_SMEM);

    // K0: weight prep (BN fold; q/k hi + exact fp32; proj hi-only)
    prep_weights<<<(MQK * K_) / 256, 256>>>(q_w, q_gamma, q_beta, q_mean, q_var,
                                            k_w, k_gamma, k_beta, k_mean, k_var,
                                            proj_w, proj_b, proj_g, proj_be, proj_m, proj_v);
    // K1: LIF(x) -> sT ([z][n][c] only)
    lif_inputT<<<dim3(N_ / 32, C_ / 32, B_), 256>>>(x, sT_p);
    // K2: qk = [Wq';Wk']_hi @ sT^T + bias (col-major B; fp16 out; repaired in K3)
    gemm_hi<true, true><<<dim3(N_ / BN, MQK / BM, T_ * B_), 256, GEMM_SMEM>>>(
        wqk_hi, sT_p, bias_qk, qk_p, MQK);
    // K3: approx spikes + exact threshold repair + attn gate -> y
    spike_attn2<<<B_ * HEADS_ * (N_ / 64), 256>>>(qk_p, m_alpha, sT_p, w32_p, bias_qk, y_p);
    // K4: out = Wp'_hi @ y + bias_p (row-major B; fp32 out)
    gemm_hi<false, false><<<dim3(N_ / BN, C_ / BM, T_ * B_), 256, GEMM_SMEM>>>(
        wp_hi, y_p, bias_p, out, C_);
}